// round 11
// baseline (speedup 1.0000x reference)
#include <cuda_runtime.h>

#define DIM 128
#define DIM4 32
#define MAX_NODES 50000
#define MAX_EDGES 800000
#define CAP 96

// ---- device scratch (allocation-free rule: __device__ globals; zero-init) --
__device__ float              g_HW[(size_t)MAX_NODES * DIM];      // 25.6 MB
__device__ unsigned long long g_bin[(size_t)MAX_NODES * CAP];     // 38.4 MB
__device__ int                g_cnt[MAX_NODES];                   // self-cleaning
__device__ int                g_ovf_cnt;                          // self-cleaning
__device__ int                g_ovf_n;                            // snapshot for ovf
__device__ int                g_ovf_r[MAX_EDGES];
__device__ unsigned long long g_ovf_e[MAX_EDGES];

#define EDGES_PER_BIN_BLOCK 512

// ---------------------------------------------------------------------------
// Fused kernel: blocks [0, n_gemm_blocks) run the GEMM path (64 rows/block,
// FFMA2, 96KB smem); blocks [n_gemm_blocks, ...) bin 512 edges each.
// The two phases are data-independent; fusing overlaps them on the chip.
// ---------------------------------------------------------------------------
__global__ void __launch_bounds__(256) fused_gemm_bin_kernel(
        const float* __restrict__ H, const float* __restrict__ W,
        const int* __restrict__ rows, const int* __restrict__ cols,
        const float* __restrict__ vals,
        int n_nodes, int n_edges, int n_gemm_blocks) {
    if ((int)blockIdx.x >= n_gemm_blocks) {
        // ---------------- bin path ----------------
        int base = ((int)blockIdx.x - n_gemm_blocks) * EDGES_PER_BIN_BLOCK
                 + (int)threadIdx.x;
#pragma unroll
        for (int t = 0; t < EDGES_PER_BIN_BLOCK / 256; t++) {
            int e = base + t * 256;
            if (e < n_edges) {
                int r = rows[e];
                unsigned long long pk = (unsigned long long)(unsigned)cols[e]
                    | ((unsigned long long)__float_as_uint(vals[e]) << 32);
                int p = atomicAdd(&g_cnt[r], 1);
                if (p < CAP) {
                    g_bin[(size_t)r * CAP + p] = pk;
                } else {
                    int q = atomicAdd(&g_ovf_cnt, 1);
                    g_ovf_r[q] = r;
                    g_ovf_e[q] = pk;
                }
            }
        }
        return;
    }

    // ---------------- GEMM path: g_HW = H @ W (FFMA2) ----------------
    extern __shared__ float smem[];
    float* sW  = smem;              // [128][128]
    float* sHT = smem + DIM * DIM;  // [128 k][64 rows] (transposed)

    const int tid  = threadIdx.x;
    const int row0 = (int)blockIdx.x * 64;

    for (int i = tid; i < DIM * DIM4; i += 256)
        ((float4*)sW)[i] = ((const float4*)W)[i];

    for (int i = tid; i < 64 * DIM4; i += 256) {
        int r  = i / DIM4;
        int k4 = (i % DIM4) * 4;
        int rr = row0 + r;
        float4 v = make_float4(0.f, 0.f, 0.f, 0.f);
        if (rr < n_nodes) v = ((const float4*)H)[(size_t)rr * DIM4 + (i % DIM4)];
        sHT[(k4 + 0) * 64 + r] = v.x;
        sHT[(k4 + 1) * 64 + r] = v.y;
        sHT[(k4 + 2) * 64 + r] = v.z;
        sHT[(k4 + 3) * 64 + r] = v.w;
    }
    __syncthreads();

    const int tr = tid >> 5;
    const int tc = tid & 31;

    unsigned long long acc[4][4];
#pragma unroll
    for (int p = 0; p < 4; p++)
#pragma unroll
        for (int j = 0; j < 4; j++) acc[p][j] = 0ull;

#pragma unroll 4
    for (int k = 0; k < DIM; k++) {
        float4 w = ((const float4*)sW)[k * DIM4 + tc];
        unsigned long long ws[4];
        asm("mov.b64 %0, {%1, %2};" : "=l"(ws[0]) : "f"(w.x), "f"(w.x));
        asm("mov.b64 %0, {%1, %2};" : "=l"(ws[1]) : "f"(w.y), "f"(w.y));
        asm("mov.b64 %0, {%1, %2};" : "=l"(ws[2]) : "f"(w.z), "f"(w.z));
        asm("mov.b64 %0, {%1, %2};" : "=l"(ws[3]) : "f"(w.w), "f"(w.w));
        const int base = k * 64 + tr * 8;
#pragma unroll
        for (int p = 0; p < 4; p++) {
            unsigned long long hp =
                *(const unsigned long long*)&sHT[base + 2 * p];
            asm("fma.rn.f32x2 %0, %1, %2, %0;" : "+l"(acc[p][0]) : "l"(hp), "l"(ws[0]));
            asm("fma.rn.f32x2 %0, %1, %2, %0;" : "+l"(acc[p][1]) : "l"(hp), "l"(ws[1]));
            asm("fma.rn.f32x2 %0, %1, %2, %0;" : "+l"(acc[p][2]) : "l"(hp), "l"(ws[2]));
            asm("fma.rn.f32x2 %0, %1, %2, %0;" : "+l"(acc[p][3]) : "l"(hp), "l"(ws[3]));
        }
    }

#pragma unroll
    for (int p = 0; p < 4; p++) {
        float2 a0 = *reinterpret_cast<float2*>(&acc[p][0]);
        float2 a1 = *reinterpret_cast<float2*>(&acc[p][1]);
        float2 a2 = *reinterpret_cast<float2*>(&acc[p][2]);
        float2 a3 = *reinterpret_cast<float2*>(&acc[p][3]);
        int rr0 = row0 + tr * 8 + 2 * p;
        int rr1 = rr0 + 1;
        if (rr0 < n_nodes)
            ((float4*)g_HW)[(size_t)rr0 * DIM4 + tc] = make_float4(a0.x, a1.x, a2.x, a3.x);
        if (rr1 < n_nodes)
            ((float4*)g_HW)[(size_t)rr1 * DIM4 + tc] = make_float4(a0.y, a1.y, a2.y, a3.y);
    }
}

// ---------------------------------------------------------------------------
// SpMM: one warp per output row (R3-proven form: broadcast LDG of bin entries,
// unroll-4 gathers; runs at the LTS bandwidth cap).
// ---------------------------------------------------------------------------
__global__ void __launch_bounds__(256) spmm_kernel(const float* __restrict__ bias,
                                                   float* __restrict__ out,
                                                   int n_nodes) {
    int gt   = blockIdx.x * blockDim.x + threadIdx.x;
    int r    = gt >> 5;
    int lane = gt & 31;
    if (r >= n_nodes) return;

    int cnt = g_cnt[r];
    if (lane == 0) g_cnt[r] = 0;                 // self-clean for next replay
    if (r == 0 && lane == 0) {                   // snapshot + reset overflow count
        g_ovf_n = g_ovf_cnt;
        g_ovf_cnt = 0;
    }
    int n = cnt > CAP ? CAP : cnt;
    const unsigned long long* bp = &g_bin[(size_t)r * CAP];

    float4 acc = ((const float4*)bias)[lane];
#pragma unroll 4
    for (int j = 0; j < n; j++) {
        unsigned long long e = bp[j];
        int   c = (int)(unsigned)e;
        float v = __uint_as_float((unsigned)(e >> 32));
        float4 hw = ((const float4*)g_HW)[(size_t)c * DIM4 + lane];
        acc.x += v * hw.x;
        acc.y += v * hw.y;
        acc.z += v * hw.z;
        acc.w += v * hw.w;
    }
    ((float4*)out)[(size_t)r * DIM4 + lane] = acc;
}

// ---------------------------------------------------------------------------
// Overflow edges (empty in practice; correctness path). Runs after spmm.
// ---------------------------------------------------------------------------
__global__ void __launch_bounds__(256) ovf_kernel(float* __restrict__ out) {
    int n = g_ovf_n;
    if (n <= 0) return;
    int warps = (gridDim.x * blockDim.x) >> 5;
    int w     = (blockIdx.x * blockDim.x + threadIdx.x) >> 5;
    int lane  = threadIdx.x & 31;
    for (int i = w; i < n; i += warps) {
        int r = g_ovf_r[i];
        unsigned long long e = g_ovf_e[i];
        int   c = (int)(unsigned)e;
        float v = __uint_as_float((unsigned)(e >> 32));
        float4 hw = ((const float4*)g_HW)[(size_t)c * DIM4 + lane];
        float* p = out + (size_t)r * DIM + lane * 4;
        asm volatile("red.global.add.v4.f32 [%0], {%1, %2, %3, %4};"
                     :: "l"(p), "f"(v * hw.x), "f"(v * hw.y), "f"(v * hw.z), "f"(v * hw.w)
                     : "memory");
    }
}

// ---------------------------------------------------------------------------
// Launch. Inputs: edge_rows, edge_cols, edge_vals, H, W, bias. Output f32.
// ---------------------------------------------------------------------------
extern "C" void kernel_launch(void* const* d_in, const int* in_sizes, int n_in,
                              void* d_out, int out_size) {
    const int*   edge_rows = (const int*)d_in[0];
    const int*   edge_cols = (const int*)d_in[1];
    const float* edge_vals = (const float*)d_in[2];
    const float* H         = (const float*)d_in[3];
    const float* W         = (const float*)d_in[4];
    const float* bias      = (const float*)d_in[5];
    float*       out       = (float*)d_out;

    const int n_edges = in_sizes[0];
    const int n_nodes = in_sizes[3] / DIM;

    const int smem_bytes = (DIM * DIM + 64 * DIM) * (int)sizeof(float);  // 96 KB
    cudaFuncSetAttribute(fused_gemm_bin_kernel,
                         cudaFuncAttributeMaxDynamicSharedMemorySize, smem_bytes);

    // 1) fused: GEMM (g_HW = H @ W) in blocks [0, gb), edge binning after
    const int gemm_blocks = (n_nodes + 63) / 64;
    const int bin_blocks  = (n_edges + EDGES_PER_BIN_BLOCK - 1) / EDGES_PER_BIN_BLOCK;
    fused_gemm_bin_kernel<<<gemm_blocks + bin_blocks, 256, smem_bytes>>>(
        H, W, edge_rows, edge_cols, edge_vals, n_nodes, n_edges, gemm_blocks);

    // 2) out = bias + row-gathered sum (no atomics), self-cleans counters
    {
        long long threads = (long long)n_nodes * 32;
        spmm_kernel<<<(int)((threads + 255) / 256), 256>>>(bias, out, n_nodes);
    }

    // 3) overflow correctness path (empty in practice)
    ovf_kernel<<<16, 256>>>(out);
}

// round 12
// speedup vs baseline: 1.1788x; 1.1788x over previous
#include <cuda_runtime.h>

#define DIM 128
#define DIM4 32
#define MAX_NODES 50000
#define MAX_EDGES 800000
#define CAP 96

// ---- device scratch (allocation-free rule: __device__ globals; zero-init) --
__device__ float              g_HW[(size_t)MAX_NODES * DIM];      // 25.6 MB
__device__ unsigned long long g_bin[(size_t)MAX_NODES * CAP];     // 38.4 MB
__device__ int                g_cnt[MAX_NODES];                   // self-cleaning
__device__ int                g_ovf_cnt;                          // self-cleaning
__device__ int                g_ovf_n;                            // snapshot for ovf
__device__ int                g_ovf_r[MAX_EDGES];
__device__ unsigned long long g_ovf_e[MAX_EDGES];

#define EDGES_PER_BIN_BLOCK 512
#define KT 64   // k-tile width (two phases cover DIM=128)

// smem: sW [KT][128] = 32KB, sHT [KT k][64 rows] = 16KB  -> 48KB, 4 CTAs/SM
#define SMEM_FLOATS (KT * DIM + KT * 64)

// ---------------------------------------------------------------------------
// Fused kernel: blocks [0, n_gemm_blocks) run the GEMM path (64 rows/block,
// FFMA2, k-tiled 48KB smem); blocks [n_gemm_blocks, ...) bin 512 edges each.
// ---------------------------------------------------------------------------
__global__ void __launch_bounds__(256, 4) fused_gemm_bin_kernel(
        const float* __restrict__ H, const float* __restrict__ W,
        const int* __restrict__ rows, const int* __restrict__ cols,
        const float* __restrict__ vals,
        int n_nodes, int n_edges, int n_gemm_blocks) {
    if ((int)blockIdx.x >= n_gemm_blocks) {
        // ---------------- bin path ----------------
        int base = ((int)blockIdx.x - n_gemm_blocks) * EDGES_PER_BIN_BLOCK
                 + (int)threadIdx.x;
#pragma unroll
        for (int t = 0; t < EDGES_PER_BIN_BLOCK / 256; t++) {
            int e = base + t * 256;
            if (e < n_edges) {
                int r = rows[e];
                unsigned long long pk = (unsigned long long)(unsigned)cols[e]
                    | ((unsigned long long)__float_as_uint(vals[e]) << 32);
                int p = atomicAdd(&g_cnt[r], 1);
                if (p < CAP) {
                    g_bin[(size_t)r * CAP + p] = pk;
                } else {
                    int q = atomicAdd(&g_ovf_cnt, 1);
                    g_ovf_r[q] = r;
                    g_ovf_e[q] = pk;
                }
            }
        }
        return;
    }

    // ---------------- GEMM path: g_HW = H @ W (FFMA2, k-tiled) ----------------
    extern __shared__ float smem[];
    float* sW  = smem;             // [KT][128]
    float* sHT = smem + KT * DIM;  // [KT k][64 rows] (transposed)

    const int tid  = threadIdx.x;
    const int row0 = (int)blockIdx.x * 64;
    const int tr   = tid >> 5;
    const int tc   = tid & 31;

    unsigned long long acc[4][4];  // [row-pair][col] packed (row 2p, row 2p+1)
#pragma unroll
    for (int p = 0; p < 4; p++)
#pragma unroll
        for (int j = 0; j < 4; j++) acc[p][j] = 0ull;

    for (int kh = 0; kh < DIM; kh += KT) {
        __syncthreads();
        // load W k-slice: KT rows x 32 float4 = 2048 float4, 8 per thread
        for (int i = tid; i < KT * DIM4; i += 256) {
            int kk = i / DIM4;
            ((float4*)sW)[i] = ((const float4*)W)[(kh + kk) * DIM4 + (i % DIM4)];
        }
        // load H tile k-slice transposed: 64 rows x KT k = 1024 float4
        for (int i = tid; i < 64 * (KT / 4); i += 256) {
            int r  = i / (KT / 4);
            int k4 = (i % (KT / 4)) * 4;
            int rr = row0 + r;
            float4 v = make_float4(0.f, 0.f, 0.f, 0.f);
            if (rr < n_nodes)
                v = ((const float4*)H)[(size_t)rr * DIM4 + (kh + k4) / 4];
            sHT[(k4 + 0) * 64 + r] = v.x;
            sHT[(k4 + 1) * 64 + r] = v.y;
            sHT[(k4 + 2) * 64 + r] = v.z;
            sHT[(k4 + 3) * 64 + r] = v.w;
        }
        __syncthreads();

#pragma unroll 2
        for (int k = 0; k < KT; k++) {
            float4 w = ((const float4*)sW)[k * DIM4 + tc];
            unsigned long long ws0, ws1, ws2, ws3;
            asm("mov.b64 %0, {%1, %2};" : "=l"(ws0) : "f"(w.x), "f"(w.x));
            asm("mov.b64 %0, {%1, %2};" : "=l"(ws1) : "f"(w.y), "f"(w.y));
            asm("mov.b64 %0, {%1, %2};" : "=l"(ws2) : "f"(w.z), "f"(w.z));
            asm("mov.b64 %0, {%1, %2};" : "=l"(ws3) : "f"(w.w), "f"(w.w));
            const int base = k * 64 + tr * 8;
#pragma unroll
            for (int p = 0; p < 4; p++) {
                unsigned long long hp =
                    *(const unsigned long long*)&sHT[base + 2 * p];
                asm("fma.rn.f32x2 %0, %1, %2, %0;" : "+l"(acc[p][0]) : "l"(hp), "l"(ws0));
                asm("fma.rn.f32x2 %0, %1, %2, %0;" : "+l"(acc[p][1]) : "l"(hp), "l"(ws1));
                asm("fma.rn.f32x2 %0, %1, %2, %0;" : "+l"(acc[p][2]) : "l"(hp), "l"(ws2));
                asm("fma.rn.f32x2 %0, %1, %2, %0;" : "+l"(acc[p][3]) : "l"(hp), "l"(ws3));
            }
        }
    }

#pragma unroll
    for (int p = 0; p < 4; p++) {
        float2 a0 = *reinterpret_cast<float2*>(&acc[p][0]);
        float2 a1 = *reinterpret_cast<float2*>(&acc[p][1]);
        float2 a2 = *reinterpret_cast<float2*>(&acc[p][2]);
        float2 a3 = *reinterpret_cast<float2*>(&acc[p][3]);
        int rr0 = row0 + tr * 8 + 2 * p;
        int rr1 = rr0 + 1;
        if (rr0 < n_nodes)
            ((float4*)g_HW)[(size_t)rr0 * DIM4 + tc] = make_float4(a0.x, a1.x, a2.x, a3.x);
        if (rr1 < n_nodes)
            ((float4*)g_HW)[(size_t)rr1 * DIM4 + tc] = make_float4(a0.y, a1.y, a2.y, a3.y);
    }
}

// ---------------------------------------------------------------------------
// SpMM: one warp per output row (R3-proven form: broadcast LDG of bin entries,
// unroll-4 gathers; runs at the LTS bandwidth cap).
// ---------------------------------------------------------------------------
__global__ void __launch_bounds__(256) spmm_kernel(const float* __restrict__ bias,
                                                   float* __restrict__ out,
                                                   int n_nodes) {
    int gt   = blockIdx.x * blockDim.x + threadIdx.x;
    int r    = gt >> 5;
    int lane = gt & 31;
    if (r >= n_nodes) return;

    int cnt = g_cnt[r];
    if (lane == 0) g_cnt[r] = 0;                 // self-clean for next replay
    if (r == 0 && lane == 0) {                   // snapshot + reset overflow count
        g_ovf_n = g_ovf_cnt;
        g_ovf_cnt = 0;
    }
    int n = cnt > CAP ? CAP : cnt;
    const unsigned long long* bp = &g_bin[(size_t)r * CAP];

    float4 acc = ((const float4*)bias)[lane];
#pragma unroll 4
    for (int j = 0; j < n; j++) {
        unsigned long long e = bp[j];
        int   c = (int)(unsigned)e;
        float v = __uint_as_float((unsigned)(e >> 32));
        float4 hw = ((const float4*)g_HW)[(size_t)c * DIM4 + lane];
        acc.x += v * hw.x;
        acc.y += v * hw.y;
        acc.z += v * hw.z;
        acc.w += v * hw.w;
    }
    ((float4*)out)[(size_t)r * DIM4 + lane] = acc;
}

// ---------------------------------------------------------------------------
// Overflow edges (empty in practice; correctness path). Runs after spmm.
// ---------------------------------------------------------------------------
__global__ void __launch_bounds__(256) ovf_kernel(float* __restrict__ out) {
    int n = g_ovf_n;
    if (n <= 0) return;
    int warps = (gridDim.x * blockDim.x) >> 5;
    int w     = (blockIdx.x * blockDim.x + threadIdx.x) >> 5;
    int lane  = threadIdx.x & 31;
    for (int i = w; i < n; i += warps) {
        int r = g_ovf_r[i];
        unsigned long long e = g_ovf_e[i];
        int   c = (int)(unsigned)e;
        float v = __uint_as_float((unsigned)(e >> 32));
        float4 hw = ((const float4*)g_HW)[(size_t)c * DIM4 + lane];
        float* p = out + (size_t)r * DIM + lane * 4;
        asm volatile("red.global.add.v4.f32 [%0], {%1, %2, %3, %4};"
                     :: "l"(p), "f"(v * hw.x), "f"(v * hw.y), "f"(v * hw.z), "f"(v * hw.w)
                     : "memory");
    }
}

// ---------------------------------------------------------------------------
// Launch. Inputs: edge_rows, edge_cols, edge_vals, H, W, bias. Output f32.
// ---------------------------------------------------------------------------
extern "C" void kernel_launch(void* const* d_in, const int* in_sizes, int n_in,
                              void* d_out, int out_size) {
    const int*   edge_rows = (const int*)d_in[0];
    const int*   edge_cols = (const int*)d_in[1];
    const float* edge_vals = (const float*)d_in[2];
    const float* H         = (const float*)d_in[3];
    const float* W         = (const float*)d_in[4];
    const float* bias      = (const float*)d_in[5];
    float*       out       = (float*)d_out;

    const int n_edges = in_sizes[0];
    const int n_nodes = in_sizes[3] / DIM;

    const int smem_bytes = SMEM_FLOATS * (int)sizeof(float);  // 48 KB
    cudaFuncSetAttribute(fused_gemm_bin_kernel,
                         cudaFuncAttributeMaxDynamicSharedMemorySize, smem_bytes);

    // 1) fused: GEMM (g_HW = H @ W) in blocks [0, gb), edge binning after
    const int gemm_blocks = (n_nodes + 63) / 64;
    const int bin_blocks  = (n_edges + EDGES_PER_BIN_BLOCK - 1) / EDGES_PER_BIN_BLOCK;
    fused_gemm_bin_kernel<<<gemm_blocks + bin_blocks, 256, smem_bytes>>>(
        H, W, edge_rows, edge_cols, edge_vals, n_nodes, n_edges, gemm_blocks);

    // 2) out = bias + row-gathered sum (no atomics), self-cleans counters
    {
        long long threads = (long long)n_nodes * 32;
        spmm_kernel<<<(int)((threads + 255) / 256), 256>>>(bias, out, n_nodes);
    }

    // 3) overflow correctness path (empty in practice)
    ovf_kernel<<<16, 256>>>(out);
}